// round 16
// baseline (speedup 1.0000x reference)
#include <cuda_runtime.h>
#include <cuda_fp16.h>
#include <cuda_bf16.h>
#include <math.h>
#include <stdint.h>

#define L_TOK   3072
#define DIM_C   1536
#define QKV_N   4608
#define HEADS_C 12
#define HD_C    128
#define FS_C    384
#define W_C     24
#define EPS_C   1e-6f
#define TILEK   96
#define WTSZ    (DIM_C * DIM_C / 8)

// ---------------- scratch ----------------
__device__ float g_qkv[L_TOK * QKV_N];
__device__ float g_bias[QKV_N];
__device__ uint4 g_xhi[L_TOK * DIM_C / 8];
__device__ uint4 g_whi[4 * WTSZ];
__device__ uint4 g_wlo[4 * WTSZ];
__device__ uint4 g_qA [L_TOK * DIM_C / 8];
__device__ uint4 g_kB [L_TOK * DIM_C / 8];
__device__ uint4 g_vHi[L_TOK * DIM_C / 8];
__device__ uint4 g_vLo[L_TOK * DIM_C / 8];

__device__ __constant__ int QBMAP[24] =
    {15,16,17,18,19,20,21,22,23, 12,13,14, 9,10,11, 6,7,8, 3,4,5, 0,1,2};

union U8h { uint4 v; __half h[8]; };

__device__ __forceinline__ uint32_t smem_u32(const void* p) {
    uint32_t a;
    asm("{ .reg .u64 t; cvta.to.shared.u64 t, %1; cvt.u32.u64 %0, t; }"
        : "=r"(a) : "l"(p));
    return a;
}
__device__ __forceinline__ void cp16(uint32_t dst, const void* src) {
    asm volatile("cp.async.cg.shared.global [%0], [%1], 16;"
                 :: "r"(dst), "l"(src) : "memory");
}
#define CP_COMMIT() asm volatile("cp.async.commit_group;" ::: "memory")
#define CP_WAIT(n)  asm volatile("cp.async.wait_group %0;" :: "n"(n) : "memory")

__device__ __forceinline__ void mma16816(float c[4], const uint32_t a[4],
                                         uint32_t b0, uint32_t b1) {
    asm volatile(
        "mma.sync.aligned.m16n8k16.row.col.f32.f16.f16.f32 "
        "{%0,%1,%2,%3}, {%4,%5,%6,%7}, {%8,%9}, {%0,%1,%2,%3};"
        : "+f"(c[0]), "+f"(c[1]), "+f"(c[2]), "+f"(c[3])
        : "r"(a[0]), "r"(a[1]), "r"(a[2]), "r"(a[3]), "r"(b0), "r"(b1));
}

// ============== fused prep: splitW4 (4608 blk) + splitA (2304) + bias (18) ==
__global__ __launch_bounds__(256) void prep_kernel(
    const float* __restrict__ x,
    const float* __restrict__ w0, const float* __restrict__ w1,
    const float* __restrict__ w2, const float* __restrict__ w3,
    const float* __restrict__ bq, const float* __restrict__ bk,
    const float* __restrict__ bv,
    uint4* __restrict__ xhi, uint4* __restrict__ whi, uint4* __restrict__ wlo,
    float* __restrict__ bias)
{
    const int bid = blockIdx.x;
    const int tid = threadIdx.x;
    if (bid < 4608) {                      // ---- splitW4 ----
        int gid = bid * 256 + tid;
        int tile = gid >> 5, lane = gid & 31;
        int widx = tile / (TILEK * TILEK);
        int r = tile - widx * (TILEK * TILEK);
        int nt2 = r / TILEK, kt = r - nt2 * TILEK;
        const float* W = (widx == 0) ? w0 : (widx == 1) ? w1
                       : (widx == 2) ? w2 : w3;
        int g = lane >> 2, tg = lane & 3;
        U8h H, L;
#pragma unroll
        for (int s2 = 0; s2 < 4; s2++) {
            int j = s2 >> 1, reg = s2 & 1;
            int n = nt2 * 16 + j * 8 + g;
            int k = kt * 16 + reg * 8 + 2 * tg;
            float2 v = *(const float2*)&W[(size_t)n * DIM_C + k];
            __half ax = __float2half_rn(v.x), ay = __float2half_rn(v.y);
            H.h[s2 * 2]     = ax;
            H.h[s2 * 2 + 1] = ay;
            L.h[s2 * 2]     = __float2half_rn(v.x - __half2float(ax));
            L.h[s2 * 2 + 1] = __float2half_rn(v.y - __half2float(ay));
        }
        whi[tile * 32 + lane] = H.v;
        wlo[tile * 32 + lane] = L.v;
    } else if (bid < 6912) {               // ---- splitA ----
        int gid = (bid - 4608) * 256 + tid;
        int tile = gid >> 5, lane = gid & 31;
        int mt = tile / TILEK, kt = tile - mt * TILEK;
        int g = lane >> 2, tg = lane & 3;
        U8h H;
#pragma unroll
        for (int s2 = 0; s2 < 4; s2++) {
            int row = mt * 16 + g + ((s2 & 1) << 3);
            int col = kt * 16 + ((s2 & 2) << 2) + 2 * tg;
            float2 v = *(const float2*)&x[(size_t)row * DIM_C + col];
            H.h[s2 * 2]     = __float2half_rn(v.x);
            H.h[s2 * 2 + 1] = __float2half_rn(v.y);
        }
        xhi[tile * 32 + lane] = H.v;
    } else {                               // ---- bias concat ----
        int i = (bid - 6912) * 256 + tid;
        if (i < QKV_N)
            bias[i] = (i < 1536) ? bq[i]
                    : (i < 3072 ? bk[i - 1536] : bv[i - 3072]);
    }
}

// ============== GEMM: 128x128 CTA, 2 CTAs/SM, chunk=3 k16, 3-stage ring ====
#define STG_U4 2304
#define GEMM_SMEM (3 * STG_U4 * 16)

__global__ __launch_bounds__(256, 2) void gemm_fp16t(
    const uint4* __restrict__ Ahi,
    const uint4* __restrict__ Bhi, const uint4* __restrict__ Blo,
    const float* __restrict__ bias, float* __restrict__ C, int N)
{
    extern __shared__ uint4 sm[];
    const int tid = threadIdx.x, wid = tid >> 5, lane = tid & 31;
    const int g = lane >> 2, tg = lane & 3;
    const int bm8  = blockIdx.y * 8;
    const int bn8  = blockIdx.x * 8;
    const int wm = (wid >> 2) * 4;
    const int wn = (wid & 3) * 2;

    float c[4][4][4];
#pragma unroll
    for (int i = 0; i < 4; i++)
#pragma unroll
        for (int j = 0; j < 4; j++)
#pragma unroll
            for (int t = 0; t < 4; t++) c[i][j][t] = 0.f;

#define LOAD_STAGE(slot, chunk) do {                                           \
    uint4* st = sm + (slot) * STG_U4;                                          \
    const int k3 = (chunk) * 3;                                                \
_Pragma("unroll")                                                              \
    for (int a = 0; a < 3; a++) {                                              \
        int idx = tid + a * 256;                                               \
        int ln = idx & 31;                                                     \
        int kt = (idx >> 5) - (((idx >> 5) * 171) >> 9) * 3;                   \
        int mt = idx / 96;                                                     \
        const uint4* src = Ahi                                                 \
            + ((size_t)(bm8 + mt) * TILEK + k3 + kt) * 32 + ln;                \
        cp16(smem_u32(st + (mt * 3 + kt) * 32 + ln), src);                     \
    }                                                                          \
_Pragma("unroll")                                                              \
    for (int b = 0; b < 6; b++) {                                              \
        int idx = tid + b * 256;                                               \
        int hl = idx >= 768; int rem = idx - hl * 768;                         \
        int ln = rem & 31;                                                     \
        int kt = (rem >> 5) - (((rem >> 5) * 171) >> 9) * 3;                   \
        int nt = rem / 96;                                                     \
        const uint4* src = (hl ? Blo : Bhi)                                    \
            + ((size_t)(bn8 + nt) * TILEK + k3 + kt) * 32 + ln;                \
        cp16(smem_u32(st + 768 + hl * 768 + (nt * 3 + kt) * 32 + ln), src);    \
    }                                                                          \
    CP_COMMIT();                                                               \
} while (0)

    const int NC = TILEK / 3;   // 32
    LOAD_STAGE(0, 0);
    LOAD_STAGE(1, 1);

    for (int ck = 0; ck < NC; ck++) {
        const int slot = ck % 3;
        if (ck + 2 < NC) { CP_WAIT(1); } else { CP_WAIT(0); }
        __syncthreads();
        if (ck + 2 < NC) LOAD_STAGE((ck + 2) % 3, ck + 2);

        const uint4* st = sm + slot * STG_U4;
#pragma unroll
        for (int kt = 0; kt < 3; kt++) {
            uint4 Ah[4], Bh[2], Bl[2];
#pragma unroll
            for (int i = 0; i < 4; i++)
                Ah[i] = st[((wm + i) * 3 + kt) * 32 + lane];
#pragma unroll
            for (int j = 0; j < 2; j++) {
                Bh[j] = st[768  + ((wn + j) * 3 + kt) * 32 + lane];
                Bl[j] = st[1536 + ((wn + j) * 3 + kt) * 32 + lane];
            }
#pragma unroll
            for (int i = 0; i < 4; i++) {
                uint32_t ah[4] = {Ah[i].x, Ah[i].y, Ah[i].z, Ah[i].w};
#pragma unroll
                for (int j = 0; j < 2; j++) {
                    mma16816(c[i][j*2],   ah, Bh[j].x, Bh[j].y);
                    mma16816(c[i][j*2+1], ah, Bh[j].z, Bh[j].w);
                    mma16816(c[i][j*2],   ah, Bl[j].x, Bl[j].y);
                    mma16816(c[i][j*2+1], ah, Bl[j].z, Bl[j].w);
                }
            }
        }
    }

#pragma unroll
    for (int i = 0; i < 4; i++) {
        int row0 = (bm8 + wm + i) * 16 + g;
#pragma unroll
        for (int j = 0; j < 4; j++) {
            int col = (bn8 + wn + (j >> 1)) * 16 + (j & 1) * 8 + 2 * tg;
            float b0 = bias[col], b1 = bias[col + 1];
            float2 v0 = make_float2(c[i][j][0] + b0, c[i][j][1] + b1);
            float2 v1 = make_float2(c[i][j][2] + b0, c[i][j][3] + b1);
            *(float2*)&C[(size_t)row0 * N + col] = v0;
            *(float2*)&C[(size_t)(row0 + 8) * N + col] = v1;
        }
    }
}

// ============== fused post: normrope (3072 blk) + convV (2304 blk) =========
__global__ __launch_bounds__(256) void post_kernel(
    const float* __restrict__ qkv,
    const float* __restrict__ freqs,
    const float* __restrict__ nqw, const float* __restrict__ nkw,
    uint4* __restrict__ qA, uint4* __restrict__ kB,
    uint4* __restrict__ vHi, uint4* __restrict__ vLo)
{
    __shared__ float shm[16 * 132];    // convV staging; normrope overlays
    const int bid = blockIdx.x;
    const int tid = threadIdx.x;

    if (bid < L_TOK) {                 // ---- normrope ----
        float* fr  = shm;              // [64]
        float* fi  = shm + 64;         // [64]
        float* red = shm + 128;        // [8]
        const int t = bid;
        const int f  = t / FS_C;
        const int rm = t % FS_C;
        const int hh = rm / W_C;
        const int ww = rm % W_C;
        const int grp = tid >> 7;
        const int gt  = tid & 127;

        if (tid < 64) {
            int c = tid;
            int row = (c < 22) ? f : ((c < 43) ? hh : ww);
            fr[c] = freqs[row * 128 + c * 2 + 0];
            fi[c] = freqs[row * 128 + c * 2 + 1];
        }

        const float* ptr = qkv + (size_t)t * QKV_N + grp * 1536;
        const float* w = grp ? nkw : nqw;
        uint4* frag = grp ? kB : qA;

        float v[12], wv[12];
        const int c0 = gt * 12;
#pragma unroll
        for (int j = 0; j < 3; j++) {
            float4 a = *(const float4*)&ptr[c0 + j * 4];
            float4 b = *(const float4*)&w[c0 + j * 4];
            v[j*4+0] = a.x; v[j*4+1] = a.y; v[j*4+2] = a.z; v[j*4+3] = a.w;
            wv[j*4+0] = b.x; wv[j*4+1] = b.y; wv[j*4+2] = b.z; wv[j*4+3] = b.w;
        }
        float ss = 0.f;
#pragma unroll
        for (int j = 0; j < 12; j++) ss += v[j] * v[j];
        {
            int lane = tid & 31, wd = tid >> 5;
#pragma unroll
            for (int o = 16; o > 0; o >>= 1)
                ss += __shfl_xor_sync(0xffffffffu, ss, o);
            if (lane == 0) red[wd] = ss;
        }
        __syncthreads();
        float tot = red[grp * 4 + 0] + red[grp * 4 + 1]
                  + red[grp * 4 + 2] + red[grp * 4 + 3];
        float rn = rsqrtf(tot * (1.0f / DIM_C) + EPS_C);

        const int t16 = t >> 4;
        const int bit = (t >> 3) & 1;
        const int gg  = t & 7;

#pragma unroll
        for (int j = 0; j < 6; j++) {
            int p = gt * 6 + j;
            int c = 2 * p;
            int cf = p & 63;
            float a = v[2*j]     * rn * wv[2*j];
            float b = v[2*j + 1] * rn * wv[2*j + 1];
            __half2 hv = __floats2half2_rn(a * fr[cf] - b * fi[cf],
                                           a * fi[cf] + b * fr[cf]);
            int h = c >> 7, ch = c & 127;
            int kt = ch >> 4, low = ch & 15;
            int colbit = low >> 3, tg = (low >> 1) & 3;
            int lane = gg * 4 + tg;
            int byteoff = grp ? (bit * 8 + colbit * 4) : (bit * 4 + colbit * 8);
            char* dst = (char*)frag
                + (size_t)(h * 1536 + t16 * 8 + kt) * 512 + lane * 16 + byteoff;
            *(__half2*)dst = hv;
        }
    } else {                            // ---- convV ----
        const int b = bid - L_TOK;
        const int h = b / 192, kt = b - h * 192;
        const float* V = qkv + 3072 + (size_t)kt * 16 * QKV_N + h * HD_C;

#pragma unroll
        for (int it = 0; it < 2; it++) {
            int idx = tid + it * 256;
            int row = idx >> 5, col4 = idx & 31;
            float4 x = *(const float4*)&V[(size_t)row * QKV_N + col4 * 4];
            *(float4*)&shm[row * 132 + col4 * 4] = x;
        }
        __syncthreads();

        const int nt2 = tid >> 5, lane = tid & 31;
        const int g = lane >> 2, tg = lane & 3;
        U8h H, L;
#pragma unroll
        for (int s2 = 0; s2 < 4; s2++) {
            int j = s2 >> 1, reg = s2 & 1;
            int dim = nt2 * 16 + j * 8 + g;
            int key = reg * 8 + 2 * tg;
            float va = shm[key * 132 + dim];
            float vb = shm[(key + 1) * 132 + dim];
            __half ax = __float2half_rn(va), ay = __float2half_rn(vb);
            H.h[s2 * 2]     = ax;
            H.h[s2 * 2 + 1] = ay;
            L.h[s2 * 2]     = __float2half_rn(va - __half2float(ax));
            L.h[s2 * 2 + 1] = __float2half_rn(vb - __half2float(ay));
        }
        size_t tile = (size_t)h * 1536 + nt2 * 192 + kt;
        vHi[tile * 32 + lane] = H.v;
        vLo[tile * 32 + lane] = L.v;
    }
}

// ================= tensor-core flash attention (2 CTAs/SM attempt) =========
#define ATTN_SMEM (2 * 3 * 1024 * 16)

__global__ __launch_bounds__(256, 2) void attn_fp16(
    const uint4* __restrict__ qA, const uint4* __restrict__ kB,
    const uint4* __restrict__ vHi, const uint4* __restrict__ vLo,
    uint4* __restrict__ aHi)
{
    extern __shared__ uint4 smA[];
    const int bi = blockIdx.x;
    const int h  = bi % HEADS_C;
    const int qb = QBMAP[bi / HEADS_C];
    const int tid = threadIdx.x, wid = tid >> 5, lane = tid & 31;
    const int mt = qb * 8 + wid;
    const float scale = 0.08838834764831844f;

    // Q fragments reloaded from gmem (L2-resident) each tile — frees 32 regs
    const size_t qbase = ((size_t)(h * 192 + mt) * 8) * 32 + lane;

    float oacc[16][4];
#pragma unroll
    for (int i = 0; i < 16; i++)
#pragma unroll
        for (int j = 0; j < 4; j++) oacc[i][j] = 0.f;
    float m0 = -1e30f, m1 = -1e30f, l0 = 0.f, l1 = 0.f;

    const int qfr   = qb / 3;
    const int sinkT = (qfr >= 5) ? 6 : 0;
    const int mainF = (qfr >= 5) ? (qfr - 4) * 6 : 0;
    const int mainT = (qfr >= 5) ? 30 : (qfr + 1) * 6;
    const int ntile = sinkT + mainT;

#define ATTN_LOAD(buf, kt0) do {                                               \
    uint4* bb = smA + (buf) * 3072;                                            \
    const uint4* kbase = kB + ((size_t)(h * 192 + (kt0) * 4) * 8) * 32;        \
_Pragma("unroll")                                                              \
    for (int j = 0; j < 4; j++) {                                              \
        int idx = tid + j * 256;                                               \
        cp16(smem_u32(bb + idx), kbase + idx);                                 \
    }                                                                          \
_Pragma("unroll")                                                              \
    for (int j = 0; j < 4; j++) {                                              \
        int idx = tid + j * 256;                                               \
        int nt2 = idx >> 7, rem = idx & 127, jj = rem >> 5, ln = rem & 31;     \
        size_t a = ((size_t)(h * 8 + nt2) * 192 + (kt0) * 4 + jj) * 32 + ln;   \
        cp16(smem_u32(bb + 1024 + idx), vHi + a);                              \
        cp16(smem_u32(bb + 2048 + idx), vLo + a);                              \
    }                                                                          \
    CP_COMMIT();                                                               \
} while (0)

    {
        const int kt0 = (0 < sinkT) ? 0 : mainF;
        ATTN_LOAD(0, kt0);
    }

    for (int t = 0; t < ntile; t++) {
        __syncthreads();
        if (t + 1 < ntile) {
            const int ktn = (t + 1 < sinkT) ? (t + 1) : mainF + (t + 1 - sinkT);
            ATTN_LOAD((t + 1) & 1, ktn);
            CP_WAIT(1);
        } else {
            CP_WAIT(0);
        }
        __syncthreads();

        const uint4* Ks = smA + (t & 1) * 3072;
        const uint4* Vh = Ks + 1024;
        const uint4* Vl = Ks + 2048;

        float sacc[8][4];
#pragma unroll
        for (int i = 0; i < 8; i++)
#pragma unroll
            for (int j = 0; j < 4; j++) sacc[i][j] = 0.f;

#pragma unroll
        for (int kt = 0; kt < 8; kt++) {
            uint4 qv = __ldg(&qA[qbase + kt * 32]);
            uint32_t qr[4] = {qv.x, qv.y, qv.z, qv.w};
#pragma unroll
            for (int n2 = 0; n2 < 4; n2++) {
                uint4 b = Ks[(n2 * 8 + kt) * 32 + lane];
                mma16816(sacc[n2*2],   qr, b.x, b.y);
                mma16816(sacc[n2*2+1], qr, b.z, b.w);
            }
        }

        float rm0 = -1e30f, rm1 = -1e30f;
#pragma unroll
        for (int nt = 0; nt < 8; nt++) {
            sacc[nt][0] *= scale; sacc[nt][1] *= scale;
            sacc[nt][2] *= scale; sacc[nt][3] *= scale;
            rm0 = fmaxf(rm0, fmaxf(sacc[nt][0], sacc[nt][1]));
            rm1 = fmaxf(rm1, fmaxf(sacc[nt][2], sacc[nt][3]));
        }
        rm0 = fmaxf(rm0, __shfl_xor_sync(0xffffffffu, rm0, 1));
        rm0 = fmaxf(rm0, __shfl_xor_sync(0xffffffffu, rm0, 2));
        rm1 = fmaxf(rm1, __shfl_xor_sync(0xffffffffu, rm1, 1));
        rm1 = fmaxf(rm1, __shfl_xor_sync(0xffffffffu, rm1, 2));

        float mn0 = fmaxf(m0, rm0), mn1 = fmaxf(m1, rm1);
        float al0 = __expf(m0 - mn0), al1 = __expf(m1 - mn1);
        m0 = mn0; m1 = mn1;

        float rs0 = 0.f, rs1 = 0.f;
        uint32_t ph0[8], ph1[8];
#pragma unroll
        for (int nt = 0; nt < 8; nt++) {
            float e0 = __expf(sacc[nt][0] - mn0);
            float e1 = __expf(sacc[nt][1] - mn0);
            float e2 = __expf(sacc[nt][2] - mn1);
            float e3 = __expf(sacc[nt][3] - mn1);
            rs0 += e0 + e1; rs1 += e2 + e3;
            __half2 p0 = __floats2half2_rn(e0, e1);
            __half2 p1 = __floats2half2_rn(e2, e3);
            ph0[nt] = *(uint32_t*)&p0;
            ph1[nt] = *(uint32_t*)&p1;
        }
        rs0 += __shfl_xor_sync(0xffffffffu, rs0, 1);
        rs0 += __shfl_xor_sync(0xffffffffu, rs0, 2);
        rs1 += __shfl_xor_sync(0xffffffffu, rs1, 1);
        rs1 += __shfl_xor_sync(0xffffffffu, rs1, 2);
        l0 = l0 * al0 + rs0;
        l1 = l1 * al1 + rs1;

#pragma unroll
        for (int nt = 0; nt < 16; nt++) {
            oacc[nt][0] *= al0; oacc[nt][1] *= al0;
            oacc[nt][2] *= al1; oacc[nt][3] *= al1;
        }

#pragma unroll
        for (int ks = 0; ks < 4; ks++) {
            uint32_t A_[4] = {ph0[2*ks], ph1[2*ks], ph0[2*ks+1], ph1[2*ks+1]};
#pragma unroll
            for (int n2 = 0; n2 < 8; n2++) {
                uint4 bh = Vh[(n2 * 4 + ks) * 32 + lane];
                mma16816(oacc[n2*2],   A_, bh.x, bh.y);
                mma16816(oacc[n2*2+1], A_, bh.z, bh.w);
                uint4 bl = Vl[(n2 * 4 + ks) * 32 + lane];
                mma16816(oacc[n2*2],   A_, bl.x, bl.y);
                mma16816(oacc[n2*2+1], A_, bl.z, bl.w);
            }
        }
    }

    float inv0 = 1.f / l0, inv1 = 1.f / l1;
#pragma unroll
    for (int nt2 = 0; nt2 < 8; nt2++) {
        U8h H;
        H.h[0] = __float2half_rn(oacc[nt2*2][0]   * inv0);
        H.h[1] = __float2half_rn(oacc[nt2*2][1]   * inv0);
        H.h[2] = __float2half_rn(oacc[nt2*2][2]   * inv1);
        H.h[3] = __float2half_rn(oacc[nt2*2][3]   * inv1);
        H.h[4] = __float2half_rn(oacc[nt2*2+1][0] * inv0);
        H.h[5] = __float2half_rn(oacc[nt2*2+1][1] * inv0);
        H.h[6] = __float2half_rn(oacc[nt2*2+1][2] * inv1);
        H.h[7] = __float2half_rn(oacc[nt2*2+1][3] * inv1);
        size_t tt = ((size_t)mt * TILEK + h * 8 + nt2) * 32 + lane;
        aHi[tt] = H.v;
    }
}

// ---------------- launch ----------------
extern "C" void kernel_launch(void* const* d_in, const int* in_sizes, int n_in,
                              void* d_out, int out_size)
{
    const float* x     = (const float*)d_in[0];
    const float* freqs = (const float*)d_in[3];
    const float* wq    = (const float*)d_in[4];
    const float* bq    = (const float*)d_in[5];
    const float* wk    = (const float*)d_in[6];
    const float* bk    = (const float*)d_in[7];
    const float* wv    = (const float*)d_in[8];
    const float* bv    = (const float*)d_in[9];
    const float* wo    = (const float*)d_in[10];
    const float* bo    = (const float*)d_in[11];
    const float* nqw   = (const float*)d_in[12];
    const float* nkw   = (const float*)d_in[13];
    float* out = (float*)d_out;

    float *qkv, *bias;
    uint4 *xhi, *whi, *wlo, *qA, *kB, *vHi, *vLo;
    cudaGetSymbolAddress((void**)&qkv,  g_qkv);
    cudaGetSymbolAddress((void**)&bias, g_bias);
    cudaGetSymbolAddress((void**)&xhi, g_xhi);
    cudaGetSymbolAddress((void**)&whi, g_whi);
    cudaGetSymbolAddress((void**)&wlo, g_wlo);
    cudaGetSymbolAddress((void**)&qA,  g_qA);
    cudaGetSymbolAddress((void**)&kB,  g_kB);
    cudaGetSymbolAddress((void**)&vHi, g_vHi);
    cudaGetSymbolAddress((void**)&vLo, g_vLo);

    cudaFuncSetAttribute(gemm_fp16t,
                         cudaFuncAttributeMaxDynamicSharedMemorySize, GEMM_SMEM);
    cudaFuncSetAttribute(attn_fp16,
                         cudaFuncAttributeMaxDynamicSharedMemorySize, ATTN_SMEM);

    prep_kernel<<<6930, 256>>>(x, wq, wk, wv, wo, bq, bk, bv,
                               xhi, whi, wlo, bias);

    dim3 gqkv(QKV_N / 128, L_TOK / 128);            // (36, 24)
    gemm_fp16t<<<gqkv, 256, GEMM_SMEM>>>(xhi, whi, wlo, bias, qkv, QKV_N);

    post_kernel<<<L_TOK + HEADS_C * 192, 256>>>(qkv, freqs, nqw, nkw,
                                                qA, kB, vHi, vLo);

    attn_fp16<<<(L_TOK / 128) * HEADS_C, 256, ATTN_SMEM>>>(qA, kB, vHi, vLo, xhi);

    dim3 gout(DIM_C / 128, L_TOK / 128);            // (12, 24)
    gemm_fp16t<<<gout, 256, GEMM_SMEM>>>(xhi, whi + 3 * WTSZ, wlo + 3 * WTSZ,
                                         bo, out, DIM_C);
}

// round 17
// speedup vs baseline: 1.0176x; 1.0176x over previous
#include <cuda_runtime.h>
#include <cuda_fp16.h>
#include <cuda_bf16.h>
#include <math.h>
#include <stdint.h>

#define L_TOK   3072
#define DIM_C   1536
#define QKV_N   4608
#define HEADS_C 12
#define HD_C    128
#define FS_C    384
#define W_C     24
#define EPS_C   1e-6f
#define TILEK   96
#define WTSZ    (DIM_C * DIM_C / 8)

// ---------------- scratch ----------------
__device__ float g_qkv[L_TOK * QKV_N];
__device__ float g_bias[QKV_N];
__device__ uint4 g_xhi[L_TOK * DIM_C / 8];
__device__ uint4 g_whi[4 * WTSZ];
__device__ uint4 g_wlo[4 * WTSZ];
__device__ uint4 g_qA [L_TOK * DIM_C / 8];
__device__ uint4 g_kB [L_TOK * DIM_C / 8];
__device__ uint4 g_vHi[L_TOK * DIM_C / 8];
__device__ uint4 g_vLo[L_TOK * DIM_C / 8];

__device__ __constant__ int QBMAP[24] =
    {15,16,17,18,19,20,21,22,23, 12,13,14, 9,10,11, 6,7,8, 3,4,5, 0,1,2};

union U8h { uint4 v; __half h[8]; };

__device__ __forceinline__ uint32_t smem_u32(const void* p) {
    uint32_t a;
    asm("{ .reg .u64 t; cvta.to.shared.u64 t, %1; cvt.u32.u64 %0, t; }"
        : "=r"(a) : "l"(p));
    return a;
}
__device__ __forceinline__ void cp16(uint32_t dst, const void* src) {
    asm volatile("cp.async.cg.shared.global [%0], [%1], 16;"
                 :: "r"(dst), "l"(src) : "memory");
}
#define CP_COMMIT() asm volatile("cp.async.commit_group;" ::: "memory")
#define CP_WAIT(n)  asm volatile("cp.async.wait_group %0;" :: "n"(n) : "memory")

__device__ __forceinline__ void mma16816(float c[4], const uint32_t a[4],
                                         uint32_t b0, uint32_t b1) {
    asm volatile(
        "mma.sync.aligned.m16n8k16.row.col.f32.f16.f16.f32 "
        "{%0,%1,%2,%3}, {%4,%5,%6,%7}, {%8,%9}, {%0,%1,%2,%3};"
        : "+f"(c[0]), "+f"(c[1]), "+f"(c[2]), "+f"(c[3])
        : "r"(a[0]), "r"(a[1]), "r"(a[2]), "r"(a[3]), "r"(b0), "r"(b1));
}

// ============== fused prep: splitW4 (4608 blk) + splitA (2304) + bias (18) ==
__global__ __launch_bounds__(256) void prep_kernel(
    const float* __restrict__ x,
    const float* __restrict__ w0, const float* __restrict__ w1,
    const float* __restrict__ w2, const float* __restrict__ w3,
    const float* __restrict__ bq, const float* __restrict__ bk,
    const float* __restrict__ bv,
    uint4* __restrict__ xhi, uint4* __restrict__ whi, uint4* __restrict__ wlo,
    float* __restrict__ bias)
{
    const int bid = blockIdx.x;
    const int tid = threadIdx.x;
    if (bid < 4608) {                      // ---- splitW4 ----
        int gid = bid * 256 + tid;
        int tile = gid >> 5, lane = gid & 31;
        int widx = tile / (TILEK * TILEK);
        int r = tile - widx * (TILEK * TILEK);
        int nt2 = r / TILEK, kt = r - nt2 * TILEK;
        const float* W = (widx == 0) ? w0 : (widx == 1) ? w1
                       : (widx == 2) ? w2 : w3;
        int g = lane >> 2, tg = lane & 3;
        U8h H, L;
#pragma unroll
        for (int s2 = 0; s2 < 4; s2++) {
            int j = s2 >> 1, reg = s2 & 1;
            int n = nt2 * 16 + j * 8 + g;
            int k = kt * 16 + reg * 8 + 2 * tg;
            float2 v = *(const float2*)&W[(size_t)n * DIM_C + k];
            __half ax = __float2half_rn(v.x), ay = __float2half_rn(v.y);
            H.h[s2 * 2]     = ax;
            H.h[s2 * 2 + 1] = ay;
            L.h[s2 * 2]     = __float2half_rn(v.x - __half2float(ax));
            L.h[s2 * 2 + 1] = __float2half_rn(v.y - __half2float(ay));
        }
        whi[tile * 32 + lane] = H.v;
        wlo[tile * 32 + lane] = L.v;
    } else if (bid < 6912) {               // ---- splitA ----
        int gid = (bid - 4608) * 256 + tid;
        int tile = gid >> 5, lane = gid & 31;
        int mt = tile / TILEK, kt = tile - mt * TILEK;
        int g = lane >> 2, tg = lane & 3;
        U8h H;
#pragma unroll
        for (int s2 = 0; s2 < 4; s2++) {
            int row = mt * 16 + g + ((s2 & 1) << 3);
            int col = kt * 16 + ((s2 & 2) << 2) + 2 * tg;
            float2 v = *(const float2*)&x[(size_t)row * DIM_C + col];
            H.h[s2 * 2]     = __float2half_rn(v.x);
            H.h[s2 * 2 + 1] = __float2half_rn(v.y);
        }
        xhi[tile * 32 + lane] = H.v;
    } else {                               // ---- bias concat ----
        int i = (bid - 6912) * 256 + tid;
        if (i < QKV_N)
            bias[i] = (i < 1536) ? bq[i]
                    : (i < 3072 ? bk[i - 1536] : bv[i - 3072]);
    }
}

// ============== GEMM: 128x128 CTA, 2 CTAs/SM, chunk=3 k16, 3-stage ring ====
#define STG_U4 2304
#define GEMM_SMEM (3 * STG_U4 * 16)

__global__ __launch_bounds__(256, 2) void gemm_fp16t(
    const uint4* __restrict__ Ahi,
    const uint4* __restrict__ Bhi, const uint4* __restrict__ Blo,
    const float* __restrict__ bias, float* __restrict__ C, int N)
{
    extern __shared__ uint4 sm[];
    const int tid = threadIdx.x, wid = tid >> 5, lane = tid & 31;
    const int g = lane >> 2, tg = lane & 3;
    const int bm8  = blockIdx.y * 8;
    const int bn8  = blockIdx.x * 8;
    const int wm = (wid >> 2) * 4;
    const int wn = (wid & 3) * 2;

    float c[4][4][4];
#pragma unroll
    for (int i = 0; i < 4; i++)
#pragma unroll
        for (int j = 0; j < 4; j++)
#pragma unroll
            for (int t = 0; t < 4; t++) c[i][j][t] = 0.f;

#define LOAD_STAGE(slot, chunk) do {                                           \
    uint4* st = sm + (slot) * STG_U4;                                          \
    const int k3 = (chunk) * 3;                                                \
_Pragma("unroll")                                                              \
    for (int a = 0; a < 3; a++) {                                              \
        int idx = tid + a * 256;                                               \
        int ln = idx & 31;                                                     \
        int kt = (idx >> 5) - (((idx >> 5) * 171) >> 9) * 3;                   \
        int mt = idx / 96;                                                     \
        const uint4* src = Ahi                                                 \
            + ((size_t)(bm8 + mt) * TILEK + k3 + kt) * 32 + ln;                \
        cp16(smem_u32(st + (mt * 3 + kt) * 32 + ln), src);                     \
    }                                                                          \
_Pragma("unroll")                                                              \
    for (int b = 0; b < 6; b++) {                                              \
        int idx = tid + b * 256;                                               \
        int hl = idx >= 768; int rem = idx - hl * 768;                         \
        int ln = rem & 31;                                                     \
        int kt = (rem >> 5) - (((rem >> 5) * 171) >> 9) * 3;                   \
        int nt = rem / 96;                                                     \
        const uint4* src = (hl ? Blo : Bhi)                                    \
            + ((size_t)(bn8 + nt) * TILEK + k3 + kt) * 32 + ln;                \
        cp16(smem_u32(st + 768 + hl * 768 + (nt * 3 + kt) * 32 + ln), src);    \
    }                                                                          \
    CP_COMMIT();                                                               \
} while (0)

    const int NC = TILEK / 3;   // 32
    LOAD_STAGE(0, 0);
    LOAD_STAGE(1, 1);

    for (int ck = 0; ck < NC; ck++) {
        const int slot = ck % 3;
        if (ck + 2 < NC) { CP_WAIT(1); } else { CP_WAIT(0); }
        __syncthreads();
        if (ck + 2 < NC) LOAD_STAGE((ck + 2) % 3, ck + 2);

        const uint4* st = sm + slot * STG_U4;
#pragma unroll
        for (int kt = 0; kt < 3; kt++) {
            uint4 Ah[4], Bh[2], Bl[2];
#pragma unroll
            for (int i = 0; i < 4; i++)
                Ah[i] = st[((wm + i) * 3 + kt) * 32 + lane];
#pragma unroll
            for (int j = 0; j < 2; j++) {
                Bh[j] = st[768  + ((wn + j) * 3 + kt) * 32 + lane];
                Bl[j] = st[1536 + ((wn + j) * 3 + kt) * 32 + lane];
            }
#pragma unroll
            for (int i = 0; i < 4; i++) {
                uint32_t ah[4] = {Ah[i].x, Ah[i].y, Ah[i].z, Ah[i].w};
#pragma unroll
                for (int j = 0; j < 2; j++) {
                    mma16816(c[i][j*2],   ah, Bh[j].x, Bh[j].y);
                    mma16816(c[i][j*2+1], ah, Bh[j].z, Bh[j].w);
                    mma16816(c[i][j*2],   ah, Bl[j].x, Bl[j].y);
                    mma16816(c[i][j*2+1], ah, Bl[j].z, Bl[j].w);
                }
            }
        }
    }

#pragma unroll
    for (int i = 0; i < 4; i++) {
        int row0 = (bm8 + wm + i) * 16 + g;
#pragma unroll
        for (int j = 0; j < 4; j++) {
            int col = (bn8 + wn + (j >> 1)) * 16 + (j & 1) * 8 + 2 * tg;
            float b0 = bias[col], b1 = bias[col + 1];
            float2 v0 = make_float2(c[i][j][0] + b0, c[i][j][1] + b1);
            float2 v1 = make_float2(c[i][j][2] + b0, c[i][j][3] + b1);
            *(float2*)&C[(size_t)row0 * N + col] = v0;
            *(float2*)&C[(size_t)(row0 + 8) * N + col] = v1;
        }
    }
}

// ============== fused post: normrope (3072 blk) + convV (2304 blk) =========
__global__ __launch_bounds__(256) void post_kernel(
    const float* __restrict__ qkv,
    const float* __restrict__ freqs,
    const float* __restrict__ nqw, const float* __restrict__ nkw,
    uint4* __restrict__ qA, uint4* __restrict__ kB,
    uint4* __restrict__ vHi, uint4* __restrict__ vLo)
{
    __shared__ float shm[16 * 132];
    const int bid = blockIdx.x;
    const int tid = threadIdx.x;

    if (bid < L_TOK) {                 // ---- normrope ----
        float* fr  = shm;
        float* fi  = shm + 64;
        float* red = shm + 128;
        const int t = bid;
        const int f  = t / FS_C;
        const int rm = t % FS_C;
        const int hh = rm / W_C;
        const int ww = rm % W_C;
        const int grp = tid >> 7;
        const int gt  = tid & 127;

        if (tid < 64) {
            int c = tid;
            int row = (c < 22) ? f : ((c < 43) ? hh : ww);
            fr[c] = freqs[row * 128 + c * 2 + 0];
            fi[c] = freqs[row * 128 + c * 2 + 1];
        }

        const float* ptr = qkv + (size_t)t * QKV_N + grp * 1536;
        const float* w = grp ? nkw : nqw;
        uint4* frag = grp ? kB : qA;

        float v[12], wv[12];
        const int c0 = gt * 12;
#pragma unroll
        for (int j = 0; j < 3; j++) {
            float4 a = *(const float4*)&ptr[c0 + j * 4];
            float4 b = *(const float4*)&w[c0 + j * 4];
            v[j*4+0] = a.x; v[j*4+1] = a.y; v[j*4+2] = a.z; v[j*4+3] = a.w;
            wv[j*4+0] = b.x; wv[j*4+1] = b.y; wv[j*4+2] = b.z; wv[j*4+3] = b.w;
        }
        float ss = 0.f;
#pragma unroll
        for (int j = 0; j < 12; j++) ss += v[j] * v[j];
        {
            int lane = tid & 31, wd = tid >> 5;
#pragma unroll
            for (int o = 16; o > 0; o >>= 1)
                ss += __shfl_xor_sync(0xffffffffu, ss, o);
            if (lane == 0) red[wd] = ss;
        }
        __syncthreads();
        float tot = red[grp * 4 + 0] + red[grp * 4 + 1]
                  + red[grp * 4 + 2] + red[grp * 4 + 3];
        float rn = rsqrtf(tot * (1.0f / DIM_C) + EPS_C);

        const int t16 = t >> 4;
        const int bit = (t >> 3) & 1;
        const int gg  = t & 7;

#pragma unroll
        for (int j = 0; j < 6; j++) {
            int p = gt * 6 + j;
            int c = 2 * p;
            int cf = p & 63;
            float a = v[2*j]     * rn * wv[2*j];
            float b = v[2*j + 1] * rn * wv[2*j + 1];
            __half2 hv = __floats2half2_rn(a * fr[cf] - b * fi[cf],
                                           a * fi[cf] + b * fr[cf]);
            int h = c >> 7, ch = c & 127;
            int kt = ch >> 4, low = ch & 15;
            int colbit = low >> 3, tg = (low >> 1) & 3;
            int lane = gg * 4 + tg;
            int byteoff = grp ? (bit * 8 + colbit * 4) : (bit * 4 + colbit * 8);
            char* dst = (char*)frag
                + (size_t)(h * 1536 + t16 * 8 + kt) * 512 + lane * 16 + byteoff;
            *(__half2*)dst = hv;
        }
    } else {                            // ---- convV ----
        const int b = bid - L_TOK;
        const int h = b / 192, kt = b - h * 192;
        const float* V = qkv + 3072 + (size_t)kt * 16 * QKV_N + h * HD_C;

#pragma unroll
        for (int it = 0; it < 2; it++) {
            int idx = tid + it * 256;
            int row = idx >> 5, col4 = idx & 31;
            float4 x = *(const float4*)&V[(size_t)row * QKV_N + col4 * 4];
            *(float4*)&shm[row * 132 + col4 * 4] = x;
        }
        __syncthreads();

        const int nt2 = tid >> 5, lane = tid & 31;
        const int g = lane >> 2, tg = lane & 3;
        U8h H, L;
#pragma unroll
        for (int s2 = 0; s2 < 4; s2++) {
            int j = s2 >> 1, reg = s2 & 1;
            int dim = nt2 * 16 + j * 8 + g;
            int key = reg * 8 + 2 * tg;
            float va = shm[key * 132 + dim];
            float vb = shm[(key + 1) * 132 + dim];
            __half ax = __float2half_rn(va), ay = __float2half_rn(vb);
            H.h[s2 * 2]     = ax;
            H.h[s2 * 2 + 1] = ay;
            L.h[s2 * 2]     = __float2half_rn(va - __half2float(ax));
            L.h[s2 * 2 + 1] = __float2half_rn(vb - __half2float(ay));
        }
        size_t tile = (size_t)h * 1536 + nt2 * 192 + kt;
        vHi[tile * 32 + lane] = H.v;
        vLo[tile * 32 + lane] = L.v;
    }
}

// ================= tensor-core flash attention (R15: Q in registers) =======
#define ATTN_SMEM (2 * 3 * 1024 * 16)

__global__ __launch_bounds__(256) void attn_fp16(
    const uint4* __restrict__ qA, const uint4* __restrict__ kB,
    const uint4* __restrict__ vHi, const uint4* __restrict__ vLo,
    uint4* __restrict__ aHi)
{
    extern __shared__ uint4 smA[];
    const int bi = blockIdx.x;
    const int h  = bi % HEADS_C;
    const int qb = QBMAP[bi / HEADS_C];
    const int tid = threadIdx.x, wid = tid >> 5, lane = tid & 31;
    const int mt = qb * 8 + wid;
    const float scale = 0.08838834764831844f;

    uint32_t qf_[8][4];
#pragma unroll
    for (int kt = 0; kt < 8; kt++) {
        uint4 qv = qA[((size_t)(h * 192 + mt) * 8 + kt) * 32 + lane];
        qf_[kt][0] = qv.x; qf_[kt][1] = qv.y; qf_[kt][2] = qv.z; qf_[kt][3] = qv.w;
    }

    float oacc[16][4];
#pragma unroll
    for (int i = 0; i < 16; i++)
#pragma unroll
        for (int j = 0; j < 4; j++) oacc[i][j] = 0.f;
    float m0 = -1e30f, m1 = -1e30f, l0 = 0.f, l1 = 0.f;

    const int qfr   = qb / 3;
    const int sinkT = (qfr >= 5) ? 6 : 0;
    const int mainF = (qfr >= 5) ? (qfr - 4) * 6 : 0;
    const int mainT = (qfr >= 5) ? 30 : (qfr + 1) * 6;
    const int ntile = sinkT + mainT;

#define ATTN_LOAD(buf, kt0) do {                                               \
    uint4* bb = smA + (buf) * 3072;                                            \
    const uint4* kbase = kB + ((size_t)(h * 192 + (kt0) * 4) * 8) * 32;        \
_Pragma("unroll")                                                              \
    for (int j = 0; j < 4; j++) {                                              \
        int idx = tid + j * 256;                                               \
        cp16(smem_u32(bb + idx), kbase + idx);                                 \
    }                                                                          \
_Pragma("unroll")                                                              \
    for (int j = 0; j < 4; j++) {                                              \
        int idx = tid + j * 256;                                               \
        int nt2 = idx >> 7, rem = idx & 127, jj = rem >> 5, ln = rem & 31;     \
        size_t a = ((size_t)(h * 8 + nt2) * 192 + (kt0) * 4 + jj) * 32 + ln;   \
        cp16(smem_u32(bb + 1024 + idx), vHi + a);                              \
        cp16(smem_u32(bb + 2048 + idx), vLo + a);                              \
    }                                                                          \
    CP_COMMIT();                                                               \
} while (0)

    {
        const int kt0 = (0 < sinkT) ? 0 : mainF;
        ATTN_LOAD(0, kt0);
    }

    for (int t = 0; t < ntile; t++) {
        __syncthreads();
        if (t + 1 < ntile) {
            const int ktn = (t + 1 < sinkT) ? (t + 1) : mainF + (t + 1 - sinkT);
            ATTN_LOAD((t + 1) & 1, ktn);
            CP_WAIT(1);
        } else {
            CP_WAIT(0);
        }
        __syncthreads();

        const uint4* Ks = smA + (t & 1) * 3072;
        const uint4* Vh = Ks + 1024;
        const uint4* Vl = Ks + 2048;

        float sacc[8][4];
#pragma unroll
        for (int i = 0; i < 8; i++)
#pragma unroll
            for (int j = 0; j < 4; j++) sacc[i][j] = 0.f;

#pragma unroll
        for (int kt = 0; kt < 8; kt++) {
#pragma unroll
            for (int n2 = 0; n2 < 4; n2++) {
                uint4 b = Ks[(n2 * 8 + kt) * 32 + lane];
                mma16816(sacc[n2*2],   qf_[kt], b.x, b.y);
                mma16816(sacc[n2*2+1], qf_[kt], b.z, b.w);
            }
        }

        float rm0 = -1e30f, rm1 = -1e30f;
#pragma unroll
        for (int nt = 0; nt < 8; nt++) {
            sacc[nt][0] *= scale; sacc[nt][1] *= scale;
            sacc[nt][2] *= scale; sacc[nt][3] *= scale;
            rm0 = fmaxf(rm0, fmaxf(sacc[nt][0], sacc[nt][1]));
            rm1 = fmaxf(rm1, fmaxf(sacc[nt][2], sacc[nt][3]));
        }
        rm0 = fmaxf(rm0, __shfl_xor_sync(0xffffffffu, rm0, 1));
        rm0 = fmaxf(rm0, __shfl_xor_sync(0xffffffffu, rm0, 2));
        rm1 = fmaxf(rm1, __shfl_xor_sync(0xffffffffu, rm1, 1));
        rm1 = fmaxf(rm1, __shfl_xor_sync(0xffffffffu, rm1, 2));

        float mn0 = fmaxf(m0, rm0), mn1 = fmaxf(m1, rm1);
        float al0 = __expf(m0 - mn0), al1 = __expf(m1 - mn1);
        m0 = mn0; m1 = mn1;

        float rs0 = 0.f, rs1 = 0.f;
        uint32_t ph0[8], ph1[8];
#pragma unroll
        for (int nt = 0; nt < 8; nt++) {
            float e0 = __expf(sacc[nt][0] - mn0);
            float e1 = __expf(sacc[nt][1] - mn0);
            float e2 = __expf(sacc[nt][2] - mn1);
            float e3 = __expf(sacc[nt][3] - mn1);
            rs0 += e0 + e1; rs1 += e2 + e3;
            __half2 p0 = __floats2half2_rn(e0, e1);
            __half2 p1 = __floats2half2_rn(e2, e3);
            ph0[nt] = *(uint32_t*)&p0;
            ph1[nt] = *(uint32_t*)&p1;
        }
        rs0 += __shfl_xor_sync(0xffffffffu, rs0, 1);
        rs0 += __shfl_xor_sync(0xffffffffu, rs0, 2);
        rs1 += __shfl_xor_sync(0xffffffffu, rs1, 1);
        rs1 += __shfl_xor_sync(0xffffffffu, rs1, 2);
        l0 = l0 * al0 + rs0;
        l1 = l1 * al1 + rs1;

#pragma unroll
        for (int nt = 0; nt < 16; nt++) {
            oacc[nt][0] *= al0; oacc[nt][1] *= al0;
            oacc[nt][2] *= al1; oacc[nt][3] *= al1;
        }

#pragma unroll
        for (int ks = 0; ks < 4; ks++) {
            uint32_t A_[4] = {ph0[2*ks], ph1[2*ks], ph0[2*ks+1], ph1[2*ks+1]};
#pragma unroll
            for (int n2 = 0; n2 < 8; n2++) {
                uint4 bh = Vh[(n2 * 4 + ks) * 32 + lane];
                mma16816(oacc[n2*2],   A_, bh.x, bh.y);
                mma16816(oacc[n2*2+1], A_, bh.z, bh.w);
                uint4 bl = Vl[(n2 * 4 + ks) * 32 + lane];
                mma16816(oacc[n2*2],   A_, bl.x, bl.y);
                mma16816(oacc[n2*2+1], A_, bl.z, bl.w);
            }
        }
    }

    float inv0 = 1.f / l0, inv1 = 1.f / l1;
#pragma unroll
    for (int nt2 = 0; nt2 < 8; nt2++) {
        U8h H;
        H.h[0] = __float2half_rn(oacc[nt2*2][0]   * inv0);
        H.h[1] = __float2half_rn(oacc[nt2*2][1]   * inv0);
        H.h[2] = __float2half_rn(oacc[nt2*2][2]   * inv1);
        H.h[3] = __float2half_rn(oacc[nt2*2][3]   * inv1);
        H.h[4] = __float2half_rn(oacc[nt2*2+1][0] * inv0);
        H.h[5] = __float2half_rn(oacc[nt2*2+1][1] * inv0);
        H.h[6] = __float2half_rn(oacc[nt2*2+1][2] * inv1);
        H.h[7] = __float2half_rn(oacc[nt2*2+1][3] * inv1);
        size_t tt = ((size_t)mt * TILEK + h * 8 + nt2) * 32 + lane;
        aHi[tt] = H.v;
    }
}

// ---------------- launch ----------------
extern "C" void kernel_launch(void* const* d_in, const int* in_sizes, int n_in,
                              void* d_out, int out_size)
{
    const float* x     = (const float*)d_in[0];
    const float* freqs = (const float*)d_in[3];
    const float* wq    = (const float*)d_in[4];
    const float* bq    = (const float*)d_in[5];
    const float* wk    = (const float*)d_in[6];
    const float* bk    = (const float*)d_in[7];
    const float* wv    = (const float*)d_in[8];
    const float* bv    = (const float*)d_in[9];
    const float* wo    = (const float*)d_in[10];
    const float* bo    = (const float*)d_in[11];
    const float* nqw   = (const float*)d_in[12];
    const float* nkw   = (const float*)d_in[13];
    float* out = (float*)d_out;

    float *qkv, *bias;
    uint4 *xhi, *whi, *wlo, *qA, *kB, *vHi, *vLo;
    cudaGetSymbolAddress((void**)&qkv,  g_qkv);
    cudaGetSymbolAddress((void**)&bias, g_bias);
    cudaGetSymbolAddress((void**)&xhi, g_xhi);
    cudaGetSymbolAddress((void**)&whi, g_whi);
    cudaGetSymbolAddress((void**)&wlo, g_wlo);
    cudaGetSymbolAddress((void**)&qA,  g_qA);
    cudaGetSymbolAddress((void**)&kB,  g_kB);
    cudaGetSymbolAddress((void**)&vHi, g_vHi);
    cudaGetSymbolAddress((void**)&vLo, g_vLo);

    cudaFuncSetAttribute(gemm_fp16t,
                         cudaFuncAttributeMaxDynamicSharedMemorySize, GEMM_SMEM);
    cudaFuncSetAttribute(attn_fp16,
                         cudaFuncAttributeMaxDynamicSharedMemorySize, ATTN_SMEM);

    prep_kernel<<<6930, 256>>>(x, wq, wk, wv, wo, bq, bk, bv,
                               xhi, whi, wlo, bias);

    dim3 gqkv(QKV_N / 128, L_TOK / 128);            // (36, 24)
    gemm_fp16t<<<gqkv, 256, GEMM_SMEM>>>(xhi, whi, wlo, bias, qkv, QKV_N);

    post_kernel<<<L_TOK + HEADS_C * 192, 256>>>(qkv, freqs, nqw, nkw,
                                                qA, kB, vHi, vLo);

    attn_fp16<<<(L_TOK / 128) * HEADS_C, 256, ATTN_SMEM>>>(qA, kB, vHi, vLo, xhi);

    dim3 gout(DIM_C / 128, L_TOK / 128);            // (12, 24)
    gemm_fp16t<<<gout, 256, GEMM_SMEM>>>(xhi, whi + 3 * WTSZ, wlo + 3 * WTSZ,
                                         bo, out, DIM_C);
}